// round 9
// baseline (speedup 1.0000x reference)
#include <cuda_runtime.h>

// Problem constants (fixed shapes)
#define M_    4096
#define NN_   16
#define G_    4
#define INF_  32
#define OUTF_ 32
#define LOCF_ 8
#define LHID_ 128
#define B_    16
#define KTOT  (M_ * NN_)   // 65536 node-neighbor pairs
#define CAP_  64           // max pairs per row (Poisson(16); P(>64) ~ 1e-20)

// Scratch (static device globals -- zero-initialized; k_row resets g_rowcnt
// each execution, so graph replays are self-consistent).
__device__ int   g_rowcnt[M_];
__device__ int   g_rowlist[M_ * CAP_];        // packed (k<<12)|j
__device__ float g_attn[KTOT * G_];           // [k][g] for float4 loads
__device__ float g_agg[B_ * M_ * G_ * INF_];  // 33.5 MB (L2-resident between kernels)

__device__ __forceinline__ float tanhf_hw(float x) {
    float r; asm("tanh.approx.f32 %0, %1;" : "=f"(r) : "f"(x)); return r;
}
__device__ __forceinline__ float rcpf(float x) {
    float r; asm("rcp.approx.f32 %0, %1;" : "=f"(r) : "f"(x)); return r;
}

__device__ __forceinline__ float softmax16(float c) {
    float m = c;
#pragma unroll
    for (int s = 8; s >= 1; s >>= 1)
        m = fmaxf(m, __shfl_xor_sync(0xffffffffu, m, s, 16));
    float e = __expf(c - m);
    float t = e;
#pragma unroll
    for (int s = 8; s >= 1; s >>= 1)
        t += __shfl_xor_sync(0xffffffffu, t, s, 16);
    return e * rcpf(t);
}

// ---------------------------------------------------------------------------
// 1) k_front: blockIdx.y < 4 -> fused MLP+softmax for graph g (2 pairs per
//    thread, HW tanh, shuffle softmax); blockIdx.y == 4 -> CSR list build
//    (no dedup here; dedup is per-row in k_row).  b2 cancels in softmax.
// ---------------------------------------------------------------------------
__global__ void __launch_bounds__(256) k_front(
        const float* __restrict__ maps, const float* __restrict__ W1,
        const float* __restrict__ b1,   const float* __restrict__ W2,
        const int* __restrict__ L_idx) {
    const int tid = threadIdx.x;

    if (blockIdx.y == G_) {                       // ---- CSR path ----
        const int base = blockIdx.x * 512 + tid;
#pragma unroll
        for (int q = 0; q < 2; q++) {
            int k = base + q * 256;
            int p = L_idx[k];
            int i = p >> 12;
            int pos = atomicAdd(&g_rowcnt[i], 1);
            if (pos < CAP_) g_rowlist[i * CAP_ + pos] = (k << 12) | (p & (M_ - 1));
        }
        return;
    }

    // ---- MLP path (identical to the measured R6 k_mlp) ----
    __shared__ float sW1[LHID_ * LOCF_];
    __shared__ float sb1[LHID_];
    __shared__ float sW2[LHID_];
    const int g = blockIdx.y;
    for (int t = tid; t < LHID_ * LOCF_; t += 256)
        sW1[t] = W1[g * LHID_ * LOCF_ + t];
    if (tid < LHID_) {
        sb1[tid] = b1[g * LHID_ + tid];
        sW2[tid] = W2[g * LHID_ + tid];
    }
    __syncthreads();

    const int k0 = blockIdx.x * 512 + tid;
    const int k1 = k0 + 256;
    const float4 p0a = reinterpret_cast<const float4*>(maps)[k0 * 2 + 0];
    const float4 p0b = reinterpret_cast<const float4*>(maps)[k0 * 2 + 1];
    const float4 p1a = reinterpret_cast<const float4*>(maps)[k1 * 2 + 0];
    const float4 p1b = reinterpret_cast<const float4*>(maps)[k1 * 2 + 1];

    float c0 = 0.0f, c1 = 0.0f;
#pragma unroll 4
    for (int j = 0; j < LHID_; j++) {
        const float4 w0 = *reinterpret_cast<const float4*>(sW1 + j * 8);
        const float4 w1 = *reinterpret_cast<const float4*>(sW1 + j * 8 + 4);
        const float bb = sb1[j];
        const float wj = sW2[j];

        float u = bb;
        u = fmaf(w0.x, p0a.x, u); u = fmaf(w0.y, p0a.y, u);
        u = fmaf(w0.z, p0a.z, u); u = fmaf(w0.w, p0a.w, u);
        u = fmaf(w1.x, p0b.x, u); u = fmaf(w1.y, p0b.y, u);
        u = fmaf(w1.z, p0b.z, u); u = fmaf(w1.w, p0b.w, u);
        float v = bb;
        v = fmaf(w0.x, p1a.x, v); v = fmaf(w0.y, p1a.y, v);
        v = fmaf(w0.z, p1a.z, v); v = fmaf(w0.w, p1a.w, v);
        v = fmaf(w1.x, p1b.x, v); v = fmaf(w1.y, p1b.y, v);
        v = fmaf(w1.z, p1b.z, v); v = fmaf(w1.w, p1b.w, v);

        c0 = fmaf(wj, tanhf_hw(u), c0);
        c1 = fmaf(wj, tanhf_hw(v), c1);
    }

    g_attn[k0 * G_ + g] = softmax16(c0);
    g_attn[k1 * G_ + g] = softmax16(c1);
}

// ---------------------------------------------------------------------------
// 2) per-row sparse aggregate with in-row dedup.  Block = row i,
//    thread = (b, f4).  Dedup: entry (k,j) is dropped (attn zeroed) if
//    another entry in the row has same j and larger k (last-write-wins,
//    matching .at[].set on duplicate L_idx -- duplicates of a flat position
//    always share the same row).
// ---------------------------------------------------------------------------
__global__ void __launch_bounds__(128) k_row(const float* __restrict__ x) {
    __shared__ int    sJ[CAP_];     // column j
    __shared__ int    sK[CAP_];     // source pair k
    __shared__ float4 sA[CAP_];     // attn[0..3] per pair
    __shared__ int    sCnt;

    const int i   = blockIdx.x;
    const int tid = threadIdx.x;
    if (tid == 0) {
        int c = g_rowcnt[i];
        sCnt = c < CAP_ ? c : CAP_;
        g_rowcnt[i] = 0;                  // reset for next replay
    }
    __syncthreads();
    const int cnt = sCnt;
    if (tid < cnt) {
        int e = g_rowlist[i * CAP_ + tid];
        sJ[tid] = e & (M_ - 1);
        sK[tid] = e >> 12;
        sA[tid] = *reinterpret_cast<const float4*>(g_attn + (e >> 12) * G_);
    }
    __syncthreads();
    if (tid < cnt) {                      // in-row last-k-wins dedup
        const int myj = sJ[tid], myk = sK[tid];
        bool keep = true;
        for (int t = 0; t < cnt; t++)
            if (sJ[t] == myj && sK[t] > myk) keep = false;
        if (!keep) sA[tid] = make_float4(0.f, 0.f, 0.f, 0.f);
    }
    __syncthreads();

    const int b = tid >> 3, f4 = tid & 7;
    const float4* xbf = reinterpret_cast<const float4*>(x) + (b << 15) + f4;

    float4 a0 = {0,0,0,0}, a1 = {0,0,0,0}, a2 = {0,0,0,0}, a3 = {0,0,0,0};
    if (cnt > 0) {
        float4 at = sA[0];
        float4 xv = xbf[sJ[0] << 3];
        for (int t = 1; t < cnt; t++) {
            const float4 an = sA[t];          // prefetch next pair
            const float4 xn = xbf[sJ[t] << 3];
            a0.x = fmaf(at.x, xv.x, a0.x); a0.y = fmaf(at.x, xv.y, a0.y);
            a0.z = fmaf(at.x, xv.z, a0.z); a0.w = fmaf(at.x, xv.w, a0.w);
            a1.x = fmaf(at.y, xv.x, a1.x); a1.y = fmaf(at.y, xv.y, a1.y);
            a1.z = fmaf(at.y, xv.z, a1.z); a1.w = fmaf(at.y, xv.w, a1.w);
            a2.x = fmaf(at.z, xv.x, a2.x); a2.y = fmaf(at.z, xv.y, a2.y);
            a2.z = fmaf(at.z, xv.z, a2.z); a2.w = fmaf(at.z, xv.w, a2.w);
            a3.x = fmaf(at.w, xv.x, a3.x); a3.y = fmaf(at.w, xv.y, a3.y);
            a3.z = fmaf(at.w, xv.z, a3.z); a3.w = fmaf(at.w, xv.w, a3.w);
            at = an; xv = xn;
        }
        a0.x = fmaf(at.x, xv.x, a0.x); a0.y = fmaf(at.x, xv.y, a0.y);
        a0.z = fmaf(at.x, xv.z, a0.z); a0.w = fmaf(at.x, xv.w, a0.w);
        a1.x = fmaf(at.y, xv.x, a1.x); a1.y = fmaf(at.y, xv.y, a1.y);
        a1.z = fmaf(at.y, xv.z, a1.z); a1.w = fmaf(at.y, xv.w, a1.w);
        a2.x = fmaf(at.z, xv.x, a2.x); a2.y = fmaf(at.z, xv.y, a2.y);
        a2.z = fmaf(at.z, xv.z, a2.z); a2.w = fmaf(at.z, xv.w, a2.w);
        a3.x = fmaf(at.w, xv.x, a3.x); a3.y = fmaf(at.w, xv.y, a3.y);
        a3.z = fmaf(at.w, xv.z, a3.z); a3.w = fmaf(at.w, xv.w, a3.w);
    }

    float4* dst = reinterpret_cast<float4*>(g_agg + ((b << 12) + i) * (G_ * INF_)) + f4;
    dst[0]  = a0;   // g=0
    dst[8]  = a1;   // g=1 (+32 floats)
    dst[16] = a2;   // g=2
    dst[24] = a3;   // g=3
}

// ---------------------------------------------------------------------------
// 3) transform: out[b,i,o] = bx[o] + sum_{g,f} agg[b,i,g,f] * Wx[g,f,o]
//    Thread = (b,i); weight reads are warp-uniform smem broadcasts.
// ---------------------------------------------------------------------------
__global__ void __launch_bounds__(256) k_xform(
        const float* __restrict__ Wx, const float* __restrict__ bx,
        float* __restrict__ out) {
    __shared__ float sWx[G_ * INF_ * OUTF_];   // 16 KB
    __shared__ float sbx[OUTF_];
    const int tid = threadIdx.x;
    for (int t = tid; t < G_ * INF_ * OUTF_; t += 256) sWx[t] = Wx[t];
    if (tid < OUTF_) sbx[tid] = bx[tid];
    __syncthreads();

    const int bi = blockIdx.x * 256 + tid;
    const float4* ap = reinterpret_cast<const float4*>(g_agg + bi * (G_ * INF_));

    float4 acc[8];
#pragma unroll
    for (int o4 = 0; o4 < 8; o4++)
        acc[o4] = *reinterpret_cast<const float4*>(sbx + o4 * 4);

#pragma unroll
    for (int g = 0; g < G_; g++) {
#pragma unroll
        for (int f4 = 0; f4 < 8; f4++) {
            float4 av = __ldg(ap + g * 8 + f4);
            const float* w = sWx + (g * INF_ + f4 * 4) * OUTF_;
#pragma unroll
            for (int o4 = 0; o4 < 8; o4++) {
                float4 w0 = *reinterpret_cast<const float4*>(w + 0 * OUTF_ + o4 * 4);
                float4 w1 = *reinterpret_cast<const float4*>(w + 1 * OUTF_ + o4 * 4);
                float4 w2 = *reinterpret_cast<const float4*>(w + 2 * OUTF_ + o4 * 4);
                float4 w3 = *reinterpret_cast<const float4*>(w + 3 * OUTF_ + o4 * 4);
                acc[o4].x = fmaf(av.x, w0.x, acc[o4].x);
                acc[o4].y = fmaf(av.x, w0.y, acc[o4].y);
                acc[o4].z = fmaf(av.x, w0.z, acc[o4].z);
                acc[o4].w = fmaf(av.x, w0.w, acc[o4].w);
                acc[o4].x = fmaf(av.y, w1.x, acc[o4].x);
                acc[o4].y = fmaf(av.y, w1.y, acc[o4].y);
                acc[o4].z = fmaf(av.y, w1.z, acc[o4].z);
                acc[o4].w = fmaf(av.y, w1.w, acc[o4].w);
                acc[o4].x = fmaf(av.z, w2.x, acc[o4].x);
                acc[o4].y = fmaf(av.z, w2.y, acc[o4].y);
                acc[o4].z = fmaf(av.z, w2.z, acc[o4].z);
                acc[o4].w = fmaf(av.z, w2.w, acc[o4].w);
                acc[o4].x = fmaf(av.w, w3.x, acc[o4].x);
                acc[o4].y = fmaf(av.w, w3.y, acc[o4].y);
                acc[o4].z = fmaf(av.w, w3.z, acc[o4].z);
                acc[o4].w = fmaf(av.w, w3.w, acc[o4].w);
            }
        }
    }

    float4* op = reinterpret_cast<float4*>(out + bi * OUTF_);
#pragma unroll
    for (int o4 = 0; o4 < 8; o4++) op[o4] = acc[o4];
}

// ---------------------------------------------------------------------------
// launch (3 kernels)
// ---------------------------------------------------------------------------
extern "C" void kernel_launch(void* const* d_in, const int* in_sizes, int n_in,
                              void* d_out, int out_size) {
    const float* x     = (const float*)d_in[0];
    const float* maps  = (const float*)d_in[1];
    const int*   L_idx = (const int*)  d_in[2];
    const float* W1    = (const float*)d_in[3];
    const float* b1    = (const float*)d_in[4];
    const float* W2    = (const float*)d_in[5];
    // d_in[6] = b2: per-graph constant shift, cancels in softmax
    const float* Wx    = (const float*)d_in[7];
    const float* bx    = (const float*)d_in[8];
    float* out = (float*)d_out;

    k_front<<<dim3(KTOT / 512, G_ + 1), 256>>>(maps, W1, b1, W2, L_idx);
    k_row<<<M_, 128>>>(x);
    k_xform<<<(B_ * M_) / 256, 256>>>(Wx, bx, out);
}